// round 12
// baseline (speedup 1.0000x reference)
#include <cuda_runtime.h>
#include <math.h>

#define NN 2048
#define LL 1024
#define NROUND 2047
#define NSWEEP 14
#define NBLK 512
#define TPB 256

// ------------------- static device scratch (no runtime allocation) -------------------
__device__ float  d_A[NN * NN];      // working symmetric matrix -> diagonalized
__device__ float  d_Vt[NN * NN];     // accumulated V^T (row k = eigenvector k)
__device__ float  d_cc[NN];          // per-column mix coefficients for current round
__device__ float  d_ss[NN];
__device__ int    d_prt[NN];         // partner column
__device__ int    d_sel[LL];         // indices of 1024 smallest eigenvalues
__device__ float  d_B[LL * LL];      // gathered M^T (B[c][r] = U[occ[r], col c])
__device__ double d_G[LL * LL];      // Gram matrix, then Cholesky factor (fp64)
__device__ double d_accLog[1];       // sum log L_ii
__device__ double d_accGauss[1];     // gaussian coherent term
__device__ double d_part[LL];        // per-row partials of the quadratic forms
__device__ unsigned d_barCnt;        // grid barrier arrival counter
__device__ volatile unsigned d_barGen;  // grid barrier generation

// ------------------- build H (symmetrized, as jnp.linalg.eigh does) -------------------
__device__ __forceinline__ float ph_dir(int i, int j, const float* Ph, const int* ivic,
                                        const float* sb, int da, int db) {
    int n1 = ivic[i * 4 + da];
    int n2 = ivic[i * 4 + db];
    if (j == n1 || j == n2) return (Ph[j] - Ph[i]) * sb[i * LL + j];
    return 0.f;
}

__global__ void build_H(const float* hm, const float* swm, const float* dwm,
                        const float* hv, const float* sv, const float* dv,
                        const float* g, const float* fS, const float* fD,
                        const float* X, const float* Y,
                        const int* ivic, const float* sb) {
    int t = blockIdx.x * blockDim.x + threadIdx.x;
    if (t >= NN * NN) return;
    int a = t / NN, b = t - a * NN;
    const float* h0m = hm;
    const float* h1m = hm + NN * NN;
    const float* h2m = hm + 2 * NN * NN;
    float base = -h1m[t] + hv[0] * h0m[t] + hv[1] * h2m[t]
               + sv[0] * swm[t] + dv[0] * dwm[t];

    int i = a & (LL - 1), j = b & (LL - 1);
    // symmetrized phonon bond matrices (reference's eigh symmetrizes its input)
    float pxs = 0.5f * (ph_dir(i, j, X, ivic, sb, 1, 3) + ph_dir(j, i, X, ivic, sb, 1, 3));
    float pys = 0.5f * (ph_dir(i, j, Y, ivic, sb, 0, 2) + ph_dir(j, i, Y, ivic, sb, 0, 2));
    float P = pxs + pys;
    float M = pxs - pys;

    float ph;
    bool ar = (a >= LL), br = (b >= LL);
    if (!ar && !br)      ph =  g[0] * P;
    else if (ar && br)   ph = -g[0] * P;
    else                 ph = fS[0] * P + fD[0] * M;

    d_A[t] = base + ph;
}

__global__ void init_vt() {
    int t = blockIdx.x * blockDim.x + threadIdx.x;
    if (t >= NN * NN) return;
    int r = t / NN, c = t - r * NN;
    d_Vt[t] = (r == c) ? 1.f : 0.f;
}

__global__ void zero_acc() {
    d_accLog[0] = 0.0;
    d_barCnt = 0;
    d_barGen = 0;
}

// ------------------- grid-wide software barrier (co-resident grid) -------------------
__device__ __forceinline__ void gsync(unsigned target) {
    __syncthreads();
    if (threadIdx.x == 0) {
        __threadfence();
        if (atomicAdd(&d_barCnt, 1u) == NBLK - 1) {
            d_barCnt = 0;
            __threadfence();
            d_barGen = target;
        } else {
            while (d_barGen < target) __nanosleep(64);
        }
    }
    __syncthreads();
}

// ------------------- persistent Jacobi: all sweeps/rounds in ONE kernel -------------------
// Each block owns pairs (blockIdx.x) and (blockIdx.x + NBLK) of the 1024 pairs per round.
// Row-only symmetric update: stage rotated rows p,q in smem, then apply all column
// rotations using only those staged rows (A'[p,j] = cc[j]*rp[j] + ss[j]*rp[prt[j]]).
__global__ __launch_bounds__(TPB, 4) void jacobi_k() {
    __shared__ float rp[NN], rq[NN];
    __shared__ float scc[NN], sss[NN];
    __shared__ int   sprt[NN];
    __shared__ int   spq[4];
    __shared__ float scs[4];
    unsigned bar = 0;

    for (int sw = 0; sw < NSWEEP; sw++)
    for (int r = 0; r < NROUND; r++) {
        // ---- phase 1: compute my 2 rotations, publish coefficients ----
        if (threadIdx.x < 2) {
            int i = blockIdx.x + threadIdx.x * NBLK;
            int p, q;
            if (i == 0) { p = r % NROUND; q = NN - 1; }
            else {
                p = (i + r) % NROUND;
                q = (NROUND - i + r) % NROUND;
            }
            float app = __ldcg(&d_A[(size_t)p * NN + p]);
            float aqq = __ldcg(&d_A[(size_t)q * NN + q]);
            float apq = __ldcg(&d_A[(size_t)p * NN + q]);
            float c = 1.f, s = 0.f;
            if (apq != 0.0f) {
                float tau = (aqq - app) / (2.f * apq);
                float t = (tau >= 0.f ? 1.f : -1.f) / (fabsf(tau) + sqrtf(1.f + tau * tau));
                c = rsqrtf(1.f + t * t);
                s = t * c;
            }
            d_cc[p] = c; d_ss[p] = -s; d_prt[p] = q;
            d_cc[q] = c; d_ss[q] =  s; d_prt[q] = p;
            spq[threadIdx.x * 2]     = p;
            spq[threadIdx.x * 2 + 1] = q;
            scs[threadIdx.x * 2]     = c;
            scs[threadIdx.x * 2 + 1] = s;
        }
        gsync(++bar);

        // ---- load this round's coefficient arrays into smem (L2-coherent reads) ----
        for (int j = threadIdx.x; j < NN; j += TPB) {
            scc[j]  = __ldcg(&d_cc[j]);
            sss[j]  = __ldcg(&d_ss[j]);
            sprt[j] = __ldcg(&d_prt[j]);
        }
        __syncthreads();

        // ---- phase 2: update my 2 pairs' rows of A and Vt ----
        for (int sub = 0; sub < 2; sub++) {
            int p = spq[sub * 2], q = spq[sub * 2 + 1];
            float c = scs[sub * 2], s = scs[sub * 2 + 1];
            float4* Ap = (float4*)(d_A  + (size_t)p * NN);
            float4* Aq = (float4*)(d_A  + (size_t)q * NN);
            float4* Vp = (float4*)(d_Vt + (size_t)p * NN);
            float4* Vq = (float4*)(d_Vt + (size_t)q * NN);
            float4* rp4 = (float4*)rp;
            float4* rq4 = (float4*)rq;
            for (int j4 = threadIdx.x; j4 < NN / 4; j4 += TPB) {
                float4 a = __ldcg(&Ap[j4]);
                float4 b = __ldcg(&Aq[j4]);
                float4 tp, tq;
                tp.x = c * a.x - s * b.x;  tq.x = s * a.x + c * b.x;
                tp.y = c * a.y - s * b.y;  tq.y = s * a.y + c * b.y;
                tp.z = c * a.z - s * b.z;  tq.z = s * a.z + c * b.z;
                tp.w = c * a.w - s * b.w;  tq.w = s * a.w + c * b.w;
                rp4[j4] = tp;
                rq4[j4] = tq;
                float4 va = __ldcg(&Vp[j4]);
                float4 vb = __ldcg(&Vq[j4]);
                float4 np, nq;
                np.x = c * va.x - s * vb.x;  nq.x = s * va.x + c * vb.x;
                np.y = c * va.y - s * vb.y;  nq.y = s * va.y + c * vb.y;
                np.z = c * va.z - s * vb.z;  nq.z = s * va.z + c * vb.z;
                np.w = c * va.w - s * vb.w;  nq.w = s * va.w + c * vb.w;
                Vp[j4] = np;
                Vq[j4] = nq;
            }
            __syncthreads();
            float* ApS = d_A + (size_t)p * NN;
            float* AqS = d_A + (size_t)q * NN;
            for (int j = threadIdx.x; j < NN; j += TPB) {
                int jp = sprt[j];
                float ccj = scc[j], ssj = sss[j];
                ApS[j] = ccj * rp[j] + ssj * rp[jp];
                AqS[j] = ccj * rq[j] + ssj * rq[jp];
            }
            __syncthreads();
        }
        gsync(++bar);
    }
}

// ------------------- select 1024 smallest eigenvalues (rank selection) -------------------
__global__ void sel_k() {
    __shared__ float ev[NN];
    int t = threadIdx.x;  // 1024
    ev[t]      = d_A[(size_t)t * NN + t];
    ev[t + LL] = d_A[(size_t)(t + LL) * NN + (t + LL)];
    __syncthreads();
    for (int kk = 0; kk < 2; kk++) {
        int k = t + kk * LL;
        float v = ev[k];
        int rank = 0;
        for (int j = 0; j < NN; j++) {
            float u = ev[j];
            rank += (u < v) || (u == v && j < k);
        }
        if (rank < LL) d_sel[rank] = k;
    }
}

// ------------------- gather B[c][r] = U[occ[r], selected col c] = Vt[sel[c]][occ[r]] ----
__global__ void gather_k(const int* occ) {
    int t = blockIdx.x * 256 + threadIdx.x;
    if (t >= LL * LL) return;
    int c = t >> 10, r = t & 1023;
    d_B[t] = d_Vt[(size_t)d_sel[c] * NN + occ[r]];
}

// ------------------- G = B * B^T (fp64 accumulate) -------------------
__global__ void gemm_k() {
    __shared__ float As[16][17], Bs[16][17];
    int tx = threadIdx.x, ty = threadIdx.y;
    int row = blockIdx.y * 16 + ty;
    int col = blockIdx.x * 16 + tx;
    double acc = 0.0;
    for (int kk = 0; kk < LL; kk += 16) {
        As[ty][tx] = d_B[(size_t)(blockIdx.y * 16 + ty) * LL + kk + tx];
        Bs[ty][tx] = d_B[(size_t)(blockIdx.x * 16 + ty) * LL + kk + tx];
        __syncthreads();
#pragma unroll
        for (int k2 = 0; k2 < 16; k2++)
            acc += (double)As[ty][k2] * (double)Bs[tx][k2];
        __syncthreads();
    }
    d_G[(size_t)row * LL + col] = acc;
}

// ------------------- blocked fp64 Cholesky (nb = 64), accumulate sum log L_ii ----------
__global__ void potf2_k(int t) {
    __shared__ double S[64][64];
    __shared__ double piv;
    int o = t * 64;
    int tid = threadIdx.x;  // 64 threads
    for (int r = 0; r < 64; r++) S[r][tid] = d_G[(size_t)(o + r) * LL + (o + tid)];
    __syncthreads();
    for (int k = 0; k < 64; k++) {
        if (tid == 0) {
            double dk = S[k][k];
            if (dk < 1e-250) dk = 1e-250;
            piv = sqrt(dk);
            S[k][k] = piv;
        }
        __syncthreads();
        double pv = piv;
        if (tid > k) S[tid][k] /= pv;
        __syncthreads();
        if (tid > k) {
            double lik = S[tid][k];
            for (int j = k + 1; j <= tid; j++) S[tid][j] -= lik * S[j][k];
        }
        __syncthreads();
    }
    if (tid == 0) {
        double ls = 0.0;
        for (int k = 0; k < 64; k++) ls += log(S[k][k]);
        d_accLog[0] += ls;   // sequential potf2 kernels: deterministic
    }
    for (int r = 0; r < 64; r++) d_G[(size_t)(o + r) * LL + (o + tid)] = S[r][tid];
}

__global__ void trsm_k(int t) {
    __shared__ double L11[64][64];
    int o = t * 64;
    int m0 = o + 64;
    int tid = threadIdx.x;  // 64
    {
        int r = tid;
        for (int c = 0; c < 64; c++) L11[r][c] = d_G[(size_t)(o + r) * LL + (o + c)];
    }
    __syncthreads();
    int row = m0 + blockIdx.x * 64 + tid;
    if (row < LL) {
        double xv[64];
        double* grow = &d_G[(size_t)row * LL + o];
        for (int c = 0; c < 64; c++) {
            double acc = grow[c];
            for (int k = 0; k < c; k++) acc -= xv[k] * L11[c][k];
            xv[c] = acc / L11[c][c];
        }
        for (int c = 0; c < 64; c++) grow[c] = xv[c];
    }
}

__global__ void syrk_k(int t) {
    __shared__ double As[16][17], Bs[16][17];
    int o = t * 64, m0 = o + 64;
    int tx = threadIdx.x, ty = threadIdx.y;
    int y = m0 + blockIdx.y * 16 + ty;
    int x = m0 + blockIdx.x * 16 + tx;
    double acc = 0.0;
    for (int kk = 0; kk < 64; kk += 16) {
        As[ty][tx] = d_G[(size_t)(m0 + blockIdx.y * 16 + ty) * LL + (o + kk + tx)];
        Bs[ty][tx] = d_G[(size_t)(m0 + blockIdx.x * 16 + ty) * LL + (o + kk + tx)];
        __syncthreads();
#pragma unroll
        for (int k2 = 0; k2 < 16; k2++) acc += As[ty][k2] * Bs[tx][k2];
        __syncthreads();
    }
    d_G[(size_t)y * LL + x] -= acc;
}

// ------------------- fused Jastrow + phonon quadratic forms -------------------
__global__ __launch_bounds__(256) void quad_k(const float* Sz, const float* X, const float* Y,
                                              const float* Js, const float* JcX, const float* JcY,
                                              const float* pXX, const float* pXY, const float* pYY,
                                              const float* sb) {
    __shared__ float sJs[289], sJcX[289], sJcY[289], sXX[289], sXY[289], sYY[289];
    __shared__ double red[256];
    int tid = threadIdx.x;
    for (int k = tid; k < 289; k += 256) {
        sJs[k]  = (k < 288) ? Js[k]  : 0.f;                    // pad_front=False
        sXX[k]  = (k < 288) ? pXX[k] : 0.f;
        sXY[k]  = (k < 288) ? pXY[k] : 0.f;
        sYY[k]  = (k < 288) ? pYY[k] : 0.f;
        sJcX[k] = (k == 0 || k >= 288) ? 0.f : JcX[k - 1];     // pad_front=True
        sJcY[k] = (k == 0 || k >= 288) ? 0.f : JcY[k - 1];
    }
    __syncthreads();
    int i = blockIdx.x;
    float xi = X[i], yi = Y[i], szi = Sz[i];
    int ix = i >> 5, iy = i & 31;
    double lsum = 0.0;
    for (int j = tid; j < LL; j += 256) {
        int jx = j >> 5, jy = j & 31;
        int dx = (jx - ix) & 31; if (dx > 16) dx = 32 - dx;
        int dy = (jy - iy) & 31; if (dy > 16) dy = 32 - dy;
        int idx = dx * 17 + dy;
        float sbij = sb[i * LL + j];
        float xj = X[j], yj = Y[j], szj = Sz[j];
        float v = szi * szj * (sJs[idx] + (sJcX[idx] * (xi - xj) + sJcY[idx] * (yi - yj)) * sbij)
                + xi * sXX[idx] * xj
                + (yi * xj + xi * yj) * sXY[idx]
                + yi * sYY[idx] * yj;
        lsum += (double)v;
    }
    red[tid] = lsum;
    __syncthreads();
    for (int st = 128; st > 0; st >>= 1) {
        if (tid < st) red[tid] += red[tid + st];
        __syncthreads();
    }
    if (tid == 0) d_part[i] = red[0];
}

__global__ void gauss_k(const float* X, const float* Y, const float* sx, const float* sy,
                        const float* zx, const float* zy, const float* xr, const float* yr) {
    __shared__ double red[1024];
    int t = threadIdx.x;
    float gx = X[t] - zx[0] * sx[t];
    float gy = Y[t] - zy[0] * sy[t];
    red[t] = -0.5 * (double)xr[0] * (double)gx * (double)gx
             - 0.5 * (double)yr[0] * (double)gy * (double)gy;
    __syncthreads();
    for (int st = 512; st > 0; st >>= 1) {
        if (t < st) red[t] += red[t + st];
        __syncthreads();
    }
    if (t == 0) d_accGauss[0] = red[0];
}

__global__ void final_k(float* out) {
    __shared__ double red[1024];
    int t = threadIdx.x;
    red[t] = d_part[t];
    __syncthreads();
    for (int st = 512; st > 0; st >>= 1) {
        if (t < st) red[t] += red[t + st];
        __syncthreads();
    }
    if (t == 0) out[0] = (float)(red[0] + d_accGauss[0] + d_accLog[0]);
}

// ------------------- launch -------------------
extern "C" void kernel_launch(void* const* d_in, const int* in_sizes, int n_in,
                              void* d_out, int out_size) {
    const int*   occ  = (const int*)d_in[0];
    // d_in[1] = xloc (unused by reference)
    const float* Sz   = (const float*)d_in[2];
    const float* X    = (const float*)d_in[3];
    const float* Y    = (const float*)d_in[4];
    const float* hv   = (const float*)d_in[5];
    const float* sv   = (const float*)d_in[6];
    const float* dv   = (const float*)d_in[7];
    const float* Js   = (const float*)d_in[8];
    const float* JcX  = (const float*)d_in[9];
    const float* JcY  = (const float*)d_in[10];
    const float* pXX  = (const float*)d_in[11];
    const float* pXY  = (const float*)d_in[12];
    const float* pYY  = (const float*)d_in[13];
    const float* g    = (const float*)d_in[14];
    const float* fS   = (const float*)d_in[15];
    const float* fD   = (const float*)d_in[16];
    const float* zx   = (const float*)d_in[17];
    const float* zy   = (const float*)d_in[18];
    const float* xr   = (const float*)d_in[19];
    const float* yr   = (const float*)d_in[20];
    const float* hm   = (const float*)d_in[21];
    const float* swm  = (const float*)d_in[22];
    const float* dwm  = (const float*)d_in[23];
    const int*   ivic = (const int*)d_in[24];
    const float* sb   = (const float*)d_in[25];
    const float* sx   = (const float*)d_in[26];
    const float* sy   = (const float*)d_in[27];
    float* out = (float*)d_out;

    int nb = (NN * NN + 255) / 256;
    build_H<<<nb, 256>>>(hm, swm, dwm, hv, sv, dv, g, fS, fD, X, Y, ivic, sb);
    init_vt<<<nb, 256>>>();
    zero_acc<<<1, 1>>>();

    // single persistent launch: all NSWEEP x NROUND Jacobi rounds
    jacobi_k<<<NBLK, TPB>>>();

    sel_k<<<1, 1024>>>();
    gather_k<<<(LL * LL + 255) / 256, 256>>>(occ);
    gemm_k<<<dim3(64, 64), dim3(16, 16)>>>();

    for (int t = 0; t < 16; t++) {
        potf2_k<<<1, 64>>>(t);
        int m = LL - (t + 1) * 64;
        if (m > 0) {
            trsm_k<<<m / 64, 64>>>(t);
            syrk_k<<<dim3(m / 16, m / 16), dim3(16, 16)>>>(t);
        }
    }

    quad_k<<<LL, 256>>>(Sz, X, Y, Js, JcX, JcY, pXX, pXY, pYY, sb);
    gauss_k<<<1, 1024>>>(X, Y, sx, sy, zx, zy, xr, yr);
    final_k<<<1, 1024>>>(out);
}

// round 13
// speedup vs baseline: 1.2999x; 1.2999x over previous
#include <cuda_runtime.h>
#include <math.h>

#define NN 2048
#define LL 1024
#define NROUND 2047
#define NSWEEP 11
#define NBLK 512
#define TPB 256

// ------------------- static device scratch (no runtime allocation) -------------------
__device__ float  d_A[NN * NN];      // working symmetric matrix -> diagonalized
__device__ float  d_Vt[NN * NN];     // accumulated V^T (row k = eigenvector k)
__device__ float2 d_cpair[LL];       // per-pair (c,s) for current round
__device__ int    d_sel[LL];         // indices of 1024 smallest eigenvalues
__device__ float  d_B2[LL * NN];     // selected eigenvector rows: B2[c][k] = Vt[sel[c]][k]
__device__ float  d_B[LL * LL];      // B[c][r] = B2[c][occ[r]]
__device__ double d_G[LL * LL];      // Gram of B   (fp64) -> Cholesky
__device__ double d_G2[LL * LL];     // Gram of B2  (fp64) -> Cholesky (orthog. correction)
__device__ double d_accLog[1];       // +sum log L_ii (G)  - sum log L_ii (G2)
__device__ double d_accGauss[1];
__device__ double d_part[LL];
__device__ unsigned d_barCnt;
__device__ volatile unsigned d_barGen;

// ------------------- build H (symmetrized, as jnp.linalg.eigh does) -------------------
__device__ __forceinline__ float ph_dir(int i, int j, const float* Ph, const int* ivic,
                                        const float* sb, int da, int db) {
    int n1 = ivic[i * 4 + da];
    int n2 = ivic[i * 4 + db];
    if (j == n1 || j == n2) return (Ph[j] - Ph[i]) * sb[i * LL + j];
    return 0.f;
}

__global__ void build_H(const float* hm, const float* swm, const float* dwm,
                        const float* hv, const float* sv, const float* dv,
                        const float* g, const float* fS, const float* fD,
                        const float* X, const float* Y,
                        const int* ivic, const float* sb) {
    int t = blockIdx.x * blockDim.x + threadIdx.x;
    if (t >= NN * NN) return;
    int a = t / NN, b = t - a * NN;
    const float* h0m = hm;
    const float* h1m = hm + NN * NN;
    const float* h2m = hm + 2 * NN * NN;
    float base = -h1m[t] + hv[0] * h0m[t] + hv[1] * h2m[t]
               + sv[0] * swm[t] + dv[0] * dwm[t];

    int i = a & (LL - 1), j = b & (LL - 1);
    float pxs = 0.5f * (ph_dir(i, j, X, ivic, sb, 1, 3) + ph_dir(j, i, X, ivic, sb, 1, 3));
    float pys = 0.5f * (ph_dir(i, j, Y, ivic, sb, 0, 2) + ph_dir(j, i, Y, ivic, sb, 0, 2));
    float P = pxs + pys;
    float M = pxs - pys;

    float ph;
    bool ar = (a >= LL), br = (b >= LL);
    if (!ar && !br)      ph =  g[0] * P;
    else if (ar && br)   ph = -g[0] * P;
    else                 ph = fS[0] * P + fD[0] * M;

    d_A[t] = base + ph;
}

__global__ void init_vt() {
    int t = blockIdx.x * blockDim.x + threadIdx.x;
    if (t >= NN * NN) return;
    int r = t / NN, c = t - r * NN;
    d_Vt[t] = (r == c) ? 1.f : 0.f;
}

__global__ void zero_acc() {
    d_accLog[0] = 0.0;
    d_barCnt = 0;
    d_barGen = 0;
}

// ------------------- grid-wide software barrier (co-resident grid) -------------------
__device__ __forceinline__ void gsync(unsigned target) {
    __syncthreads();
    if (threadIdx.x == 0) {
        __threadfence();
        if (atomicAdd(&d_barCnt, 1u) == NBLK - 1) {
            d_barCnt = 0;
            __threadfence();
            d_barGen = target;
        } else {
            while (d_barGen < target) __nanosleep(32);
        }
    }
    __syncthreads();
}

// ------------------- persistent Jacobi: all sweeps/rounds in ONE kernel -------------------
// Block bi owns pairs bi and bi+NBLK of the 1024 round-robin pairs per round.
// Per-pair (c,s) published globally; partner column jp and p/q role derived analytically:
//   u = (j - r) mod 2047 ; p-role iff u <= 1023 ; jp = (2r - j) mod 2047 ; col 2047 = q of pair 0.
__global__ __launch_bounds__(TPB, 4) void jacobi_k() {
    __shared__ float  r0p[NN], r0q[NN], r1p[NN], r1q[NN];
    __shared__ float2 scs[LL];
    __shared__ int    spq[4];
    __shared__ float  scv[4];
    unsigned bar = 0;

    for (int sw = 0; sw < NSWEEP; sw++)
    for (int r = 0; r < NROUND; r++) {
        // ---- phase 1: compute my 2 rotations, publish per-pair (c,s) ----
        if (threadIdx.x < 2) {
            int i = blockIdx.x + threadIdx.x * NBLK;
            int p, q;
            if (i == 0) { p = r % NROUND; q = NN - 1; }
            else {
                p = (i + r) % NROUND;
                q = (NROUND - i + r) % NROUND;
            }
            float app = __ldcg(&d_A[(size_t)p * NN + p]);
            float aqq = __ldcg(&d_A[(size_t)q * NN + q]);
            float apq = __ldcg(&d_A[(size_t)p * NN + q]);
            float c = 1.f, s = 0.f;
            if (apq != 0.0f) {
                float tau = (aqq - app) / (2.f * apq);
                float t = (tau >= 0.f ? 1.f : -1.f) / (fabsf(tau) + sqrtf(1.f + tau * tau));
                c = rsqrtf(1.f + t * t);
                s = t * c;
            }
            d_cpair[i] = make_float2(c, s);
            spq[threadIdx.x * 2]     = p;
            spq[threadIdx.x * 2 + 1] = q;
            scv[threadIdx.x * 2]     = c;
            scv[threadIdx.x * 2 + 1] = s;
        }
        gsync(++bar);

        int p0 = spq[0], q0 = spq[1], p1 = spq[2], q1 = spq[3];
        float c0 = scv[0], s0 = scv[1], c1 = scv[2], s1 = scv[3];

        // ---- stage: per-pair coeffs -> smem ----
        for (int k = threadIdx.x; k < LL; k += TPB)
            scs[k] = __ldcg(&d_cpair[k]);

        // ---- stage: rotate both pairs' A rows into smem ----
        {
            const float4* A0p = (const float4*)(d_A + (size_t)p0 * NN);
            const float4* A0q = (const float4*)(d_A + (size_t)q0 * NN);
            const float4* A1p = (const float4*)(d_A + (size_t)p1 * NN);
            const float4* A1q = (const float4*)(d_A + (size_t)q1 * NN);
            float4* s0p = (float4*)r0p; float4* s0q = (float4*)r0q;
            float4* s1p = (float4*)r1p; float4* s1q = (float4*)r1q;
            #pragma unroll
            for (int it = 0; it < NN / 4 / TPB; it++) {
                int j4 = threadIdx.x + it * TPB;
                float4 a0 = __ldcg(&A0p[j4]);
                float4 b0 = __ldcg(&A0q[j4]);
                float4 a1 = __ldcg(&A1p[j4]);
                float4 b1 = __ldcg(&A1q[j4]);
                float4 t0p, t0q, t1p, t1q;
                t0p.x = c0*a0.x - s0*b0.x;  t0q.x = s0*a0.x + c0*b0.x;
                t0p.y = c0*a0.y - s0*b0.y;  t0q.y = s0*a0.y + c0*b0.y;
                t0p.z = c0*a0.z - s0*b0.z;  t0q.z = s0*a0.z + c0*b0.z;
                t0p.w = c0*a0.w - s0*b0.w;  t0q.w = s0*a0.w + c0*b0.w;
                t1p.x = c1*a1.x - s1*b1.x;  t1q.x = s1*a1.x + c1*b1.x;
                t1p.y = c1*a1.y - s1*b1.y;  t1q.y = s1*a1.y + c1*b1.y;
                t1p.z = c1*a1.z - s1*b1.z;  t1q.z = s1*a1.z + c1*b1.z;
                t1p.w = c1*a1.w - s1*b1.w;  t1q.w = s1*a1.w + c1*b1.w;
                s0p[j4] = t0p; s0q[j4] = t0q; s1p[j4] = t1p; s1q[j4] = t1q;
            }
        }

        // ---- Vt rows: rotate fully in place (no column mixing needed) ----
        {
            float4* V0p = (float4*)(d_Vt + (size_t)p0 * NN);
            float4* V0q = (float4*)(d_Vt + (size_t)q0 * NN);
            float4* V1p = (float4*)(d_Vt + (size_t)p1 * NN);
            float4* V1q = (float4*)(d_Vt + (size_t)q1 * NN);
            #pragma unroll
            for (int it = 0; it < NN / 4 / TPB; it++) {
                int j4 = threadIdx.x + it * TPB;
                float4 a0 = __ldcg(&V0p[j4]);
                float4 b0 = __ldcg(&V0q[j4]);
                float4 n0p, n0q;
                n0p.x = c0*a0.x - s0*b0.x;  n0q.x = s0*a0.x + c0*b0.x;
                n0p.y = c0*a0.y - s0*b0.y;  n0q.y = s0*a0.y + c0*b0.y;
                n0p.z = c0*a0.z - s0*b0.z;  n0q.z = s0*a0.z + c0*b0.z;
                n0p.w = c0*a0.w - s0*b0.w;  n0q.w = s0*a0.w + c0*b0.w;
                __stcg(&V0p[j4], n0p);
                __stcg(&V0q[j4], n0q);
                float4 a1 = __ldcg(&V1p[j4]);
                float4 b1 = __ldcg(&V1q[j4]);
                float4 n1p, n1q;
                n1p.x = c1*a1.x - s1*b1.x;  n1q.x = s1*a1.x + c1*b1.x;
                n1p.y = c1*a1.y - s1*b1.y;  n1q.y = s1*a1.y + c1*b1.y;
                n1p.z = c1*a1.z - s1*b1.z;  n1q.z = s1*a1.z + c1*b1.z;
                n1p.w = c1*a1.w - s1*b1.w;  n1q.w = s1*a1.w + c1*b1.w;
                __stcg(&V1p[j4], n1p);
                __stcg(&V1q[j4], n1q);
            }
        }
        __syncthreads();

        // ---- mix phase: apply all column rotations, write 4 A rows ----
        {
            float* A0p = d_A + (size_t)p0 * NN;
            float* A0q = d_A + (size_t)q0 * NN;
            float* A1p = d_A + (size_t)p1 * NN;
            float* A1q = d_A + (size_t)q1 * NN;
            #pragma unroll
            for (int it = 0; it < NN / TPB; it++) {
                int j = threadIdx.x + it * TPB;
                int jp, pidx;
                bool prole;
                if (j == NN - 1) { jp = r % NROUND; prole = false; pidx = 0; }
                else {
                    int u = j - r; if (u < 0) u += NROUND;
                    if (u == 0) { jp = NN - 1; prole = true; pidx = 0; }
                    else {
                        int t2 = 2 * r - j;
                        if (t2 < 0)       t2 += NROUND;
                        if (t2 >= NROUND) t2 -= NROUND;
                        jp = t2;
                        prole = (u <= 1023);
                        pidx = prole ? u : NROUND - u;
                    }
                }
                float2 cs = scs[pidx];
                float ccj = cs.x;
                float ssj = prole ? -cs.y : cs.y;
                __stcg(&A0p[j], ccj * r0p[j] + ssj * r0p[jp]);
                __stcg(&A0q[j], ccj * r0q[j] + ssj * r0q[jp]);
                __stcg(&A1p[j], ccj * r1p[j] + ssj * r1p[jp]);
                __stcg(&A1q[j], ccj * r1q[j] + ssj * r1q[jp]);
            }
        }
        gsync(++bar);
    }
}

// ------------------- select 1024 smallest eigenvalues (rank selection) -------------------
__global__ void sel_k() {
    __shared__ float ev[NN];
    int t = threadIdx.x;  // 1024
    ev[t]      = d_A[(size_t)t * NN + t];
    ev[t + LL] = d_A[(size_t)(t + LL) * NN + (t + LL)];
    __syncthreads();
    for (int kk = 0; kk < 2; kk++) {
        int k = t + kk * LL;
        float v = ev[k];
        int rank = 0;
        for (int j = 0; j < NN; j++) {
            float u = ev[j];
            rank += (u < v) || (u == v && j < k);
        }
        if (rank < LL) d_sel[rank] = k;
    }
}

// ------------------- gather selected eigenvector rows -------------------
__global__ void gather2_k() {
    int t = blockIdx.x * 256 + threadIdx.x;
    if (t >= LL * NN) return;
    int c = t >> 11, k = t & (NN - 1);
    d_B2[t] = d_Vt[(size_t)d_sel[c] * NN + k];
}

__global__ void gatherB_k(const int* occ) {
    int t = blockIdx.x * 256 + threadIdx.x;
    if (t >= LL * LL) return;
    int c = t >> 10, rr = t & 1023;
    d_B[t] = d_B2[(size_t)c * NN + occ[rr]];
}

// ------------------- Gram = S * S^T (fp64 accumulate); which=0: B (K=1024)->G, 1: B2 (K=2048)->G2
__global__ void gram_k(int which) {
    __shared__ float As[16][17], Bs[16][17];
    const float* S = which ? d_B2 : d_B;
    double* G = which ? d_G2 : d_G;
    int K = which ? NN : LL;
    int tx = threadIdx.x, ty = threadIdx.y;
    int row = blockIdx.y * 16 + ty;
    int col = blockIdx.x * 16 + tx;
    double acc = 0.0;
    for (int kk = 0; kk < K; kk += 16) {
        As[ty][tx] = S[(size_t)(blockIdx.y * 16 + ty) * K + kk + tx];
        Bs[ty][tx] = S[(size_t)(blockIdx.x * 16 + ty) * K + kk + tx];
        __syncthreads();
#pragma unroll
        for (int k2 = 0; k2 < 16; k2++)
            acc += (double)As[ty][k2] * (double)Bs[tx][k2];
        __syncthreads();
    }
    G[(size_t)row * LL + col] = acc;
}

// ------------------- blocked fp64 Cholesky (nb=64); which selects matrix; sign on logdet ----
__global__ void potf2_k(int t, int which) {
    __shared__ double S[64][64];
    __shared__ double piv;
    double* G = which ? d_G2 : d_G;
    double sgn = which ? -1.0 : 1.0;
    int o = t * 64;
    int tid = threadIdx.x;  // 64 threads
    for (int r = 0; r < 64; r++) S[r][tid] = G[(size_t)(o + r) * LL + (o + tid)];
    __syncthreads();
    for (int k = 0; k < 64; k++) {
        if (tid == 0) {
            double dk = S[k][k];
            if (dk < 1e-250) dk = 1e-250;
            piv = sqrt(dk);
            S[k][k] = piv;
        }
        __syncthreads();
        double pv = piv;
        if (tid > k) S[tid][k] /= pv;
        __syncthreads();
        if (tid > k) {
            double lik = S[tid][k];
            for (int j = k + 1; j <= tid; j++) S[tid][j] -= lik * S[j][k];
        }
        __syncthreads();
    }
    if (tid == 0) {
        double ls = 0.0;
        for (int k = 0; k < 64; k++) ls += log(S[k][k]);
        d_accLog[0] += sgn * ls;   // sequential potf2 kernels: deterministic
    }
    for (int r = 0; r < 64; r++) G[(size_t)(o + r) * LL + (o + tid)] = S[r][tid];
}

__global__ void trsm_k(int t, int which) {
    __shared__ double L11[64][64];
    double* G = which ? d_G2 : d_G;
    int o = t * 64;
    int m0 = o + 64;
    int tid = threadIdx.x;  // 64
    {
        int r = tid;
        for (int c = 0; c < 64; c++) L11[r][c] = G[(size_t)(o + r) * LL + (o + c)];
    }
    __syncthreads();
    int row = m0 + blockIdx.x * 64 + tid;
    if (row < LL) {
        double xv[64];
        double* grow = &G[(size_t)row * LL + o];
        for (int c = 0; c < 64; c++) {
            double acc = grow[c];
            for (int k = 0; k < c; k++) acc -= xv[k] * L11[c][k];
            xv[c] = acc / L11[c][c];
        }
        for (int c = 0; c < 64; c++) grow[c] = xv[c];
    }
}

__global__ void syrk_k(int t, int which) {
    __shared__ double As[16][17], Bs[16][17];
    double* G = which ? d_G2 : d_G;
    int o = t * 64, m0 = o + 64;
    int tx = threadIdx.x, ty = threadIdx.y;
    int y = m0 + blockIdx.y * 16 + ty;
    int x = m0 + blockIdx.x * 16 + tx;
    double acc = 0.0;
    for (int kk = 0; kk < 64; kk += 16) {
        As[ty][tx] = G[(size_t)(m0 + blockIdx.y * 16 + ty) * LL + (o + kk + tx)];
        Bs[ty][tx] = G[(size_t)(m0 + blockIdx.x * 16 + ty) * LL + (o + kk + tx)];
        __syncthreads();
#pragma unroll
        for (int k2 = 0; k2 < 16; k2++) acc += As[ty][k2] * Bs[tx][k2];
        __syncthreads();
    }
    G[(size_t)y * LL + x] -= acc;
}

// ------------------- fused Jastrow + phonon quadratic forms -------------------
__global__ __launch_bounds__(256) void quad_k(const float* Sz, const float* X, const float* Y,
                                              const float* Js, const float* JcX, const float* JcY,
                                              const float* pXX, const float* pXY, const float* pYY,
                                              const float* sb) {
    __shared__ float sJs[289], sJcX[289], sJcY[289], sXX[289], sXY[289], sYY[289];
    __shared__ double red[256];
    int tid = threadIdx.x;
    for (int k = tid; k < 289; k += 256) {
        sJs[k]  = (k < 288) ? Js[k]  : 0.f;                    // pad_front=False
        sXX[k]  = (k < 288) ? pXX[k] : 0.f;
        sXY[k]  = (k < 288) ? pXY[k] : 0.f;
        sYY[k]  = (k < 288) ? pYY[k] : 0.f;
        sJcX[k] = (k == 0 || k >= 288) ? 0.f : JcX[k - 1];     // pad_front=True
        sJcY[k] = (k == 0 || k >= 288) ? 0.f : JcY[k - 1];
    }
    __syncthreads();
    int i = blockIdx.x;
    float xi = X[i], yi = Y[i], szi = Sz[i];
    int ix = i >> 5, iy = i & 31;
    double lsum = 0.0;
    for (int j = tid; j < LL; j += 256) {
        int jx = j >> 5, jy = j & 31;
        int dx = (jx - ix) & 31; if (dx > 16) dx = 32 - dx;
        int dy = (jy - iy) & 31; if (dy > 16) dy = 32 - dy;
        int idx = dx * 17 + dy;
        float sbij = sb[i * LL + j];
        float xj = X[j], yj = Y[j], szj = Sz[j];
        float v = szi * szj * (sJs[idx] + (sJcX[idx] * (xi - xj) + sJcY[idx] * (yi - yj)) * sbij)
                + xi * sXX[idx] * xj
                + (yi * xj + xi * yj) * sXY[idx]
                + yi * sYY[idx] * yj;
        lsum += (double)v;
    }
    red[tid] = lsum;
    __syncthreads();
    for (int st = 128; st > 0; st >>= 1) {
        if (tid < st) red[tid] += red[tid + st];
        __syncthreads();
    }
    if (tid == 0) d_part[i] = red[0];
}

__global__ void gauss_k(const float* X, const float* Y, const float* sx, const float* sy,
                        const float* zx, const float* zy, const float* xr, const float* yr) {
    __shared__ double red[1024];
    int t = threadIdx.x;
    float gx = X[t] - zx[0] * sx[t];
    float gy = Y[t] - zy[0] * sy[t];
    red[t] = -0.5 * (double)xr[0] * (double)gx * (double)gx
             - 0.5 * (double)yr[0] * (double)gy * (double)gy;
    __syncthreads();
    for (int st = 512; st > 0; st >>= 1) {
        if (t < st) red[t] += red[t + st];
        __syncthreads();
    }
    if (t == 0) d_accGauss[0] = red[0];
}

__global__ void final_k(float* out) {
    __shared__ double red[1024];
    int t = threadIdx.x;
    red[t] = d_part[t];
    __syncthreads();
    for (int st = 512; st > 0; st >>= 1) {
        if (t < st) red[t] += red[t + st];
        __syncthreads();
    }
    if (t == 0) out[0] = (float)(red[0] + d_accGauss[0] + d_accLog[0]);
}

// ------------------- launch -------------------
extern "C" void kernel_launch(void* const* d_in, const int* in_sizes, int n_in,
                              void* d_out, int out_size) {
    const int*   occ  = (const int*)d_in[0];
    // d_in[1] = xloc (unused by reference)
    const float* Sz   = (const float*)d_in[2];
    const float* X    = (const float*)d_in[3];
    const float* Y    = (const float*)d_in[4];
    const float* hv   = (const float*)d_in[5];
    const float* sv   = (const float*)d_in[6];
    const float* dv   = (const float*)d_in[7];
    const float* Js   = (const float*)d_in[8];
    const float* JcX  = (const float*)d_in[9];
    const float* JcY  = (const float*)d_in[10];
    const float* pXX  = (const float*)d_in[11];
    const float* pXY  = (const float*)d_in[12];
    const float* pYY  = (const float*)d_in[13];
    const float* g    = (const float*)d_in[14];
    const float* fS   = (const float*)d_in[15];
    const float* fD   = (const float*)d_in[16];
    const float* zx   = (const float*)d_in[17];
    const float* zy   = (const float*)d_in[18];
    const float* xr   = (const float*)d_in[19];
    const float* yr   = (const float*)d_in[20];
    const float* hm   = (const float*)d_in[21];
    const float* swm  = (const float*)d_in[22];
    const float* dwm  = (const float*)d_in[23];
    const int*   ivic = (const int*)d_in[24];
    const float* sb   = (const float*)d_in[25];
    const float* sx   = (const float*)d_in[26];
    const float* sy   = (const float*)d_in[27];
    float* out = (float*)d_out;

    int nb = (NN * NN + 255) / 256;
    build_H<<<nb, 256>>>(hm, swm, dwm, hv, sv, dv, g, fS, fD, X, Y, ivic, sb);
    init_vt<<<nb, 256>>>();
    zero_acc<<<1, 1>>>();

    // single persistent launch: all NSWEEP x NROUND Jacobi rounds
    jacobi_k<<<NBLK, TPB>>>();

    sel_k<<<1, 1024>>>();
    gather2_k<<<(LL * NN + 255) / 256, 256>>>();
    gatherB_k<<<(LL * LL + 255) / 256, 256>>>(occ);
    gram_k<<<dim3(64, 64), dim3(16, 16)>>>(0);
    gram_k<<<dim3(64, 64), dim3(16, 16)>>>(1);

    for (int which = 0; which < 2; which++) {
        for (int t = 0; t < 16; t++) {
            potf2_k<<<1, 64>>>(t, which);
            int m = LL - (t + 1) * 64;
            if (m > 0) {
                trsm_k<<<m / 64, 64>>>(t, which);
                syrk_k<<<dim3(m / 16, m / 16), dim3(16, 16)>>>(t, which);
            }
        }
    }

    quad_k<<<LL, 256>>>(Sz, X, Y, Js, JcX, JcY, pXX, pXY, pYY, sb);
    gauss_k<<<1, 1024>>>(X, Y, sx, sy, zx, zy, xr, yr);
    final_k<<<1, 1024>>>(out);
}

// round 14
// speedup vs baseline: 1.3667x; 1.0514x over previous
#include <cuda_runtime.h>
#include <math.h>

#define NN 2048
#define LL 1024
#define NROUND 2047
#define NSWEEP 10
#define NBLK 512
#define TPB 256

// ------------------- static device scratch (no runtime allocation) -------------------
__device__ float  d_A[NN * NN];      // working symmetric matrix -> diagonalized
__device__ float  d_Vt[NN * NN];     // accumulated V^T (row k = eigenvector k)
__device__ float  d_rotA[2][LL];     // next-round rotation scalars: app (parity buffered)
__device__ float  d_rotB[2][LL];     // aqq
__device__ float  d_rotC[2][LL];     // apq
__device__ int    d_sel[LL];         // indices of 1024 smallest eigenvalues
__device__ float  d_B2[LL * NN];     // selected eigenvector rows: B2[c][k] = Vt[sel[c]][k]
__device__ float  d_B[LL * LL];      // B[c][r] = B2[c][occ[r]]
__device__ double d_G[LL * LL];      // Gram of B   (fp64) -> Cholesky
__device__ double d_G2[LL * LL];     // Gram of B2  (fp64) -> Cholesky (orthog. correction)
__device__ double d_accLog[1];       // +sum log L_ii (G)  - sum log L_ii (G2)
__device__ double d_accGauss[1];
__device__ double d_part[LL];
__device__ unsigned d_barCnt;
__device__ volatile unsigned d_barGen;

// ------------------- build H (symmetrized, as jnp.linalg.eigh does) -------------------
__device__ __forceinline__ float ph_dir(int i, int j, const float* Ph, const int* ivic,
                                        const float* sb, int da, int db) {
    int n1 = ivic[i * 4 + da];
    int n2 = ivic[i * 4 + db];
    if (j == n1 || j == n2) return (Ph[j] - Ph[i]) * sb[i * LL + j];
    return 0.f;
}

__global__ void build_H(const float* hm, const float* swm, const float* dwm,
                        const float* hv, const float* sv, const float* dv,
                        const float* g, const float* fS, const float* fD,
                        const float* X, const float* Y,
                        const int* ivic, const float* sb) {
    int t = blockIdx.x * blockDim.x + threadIdx.x;
    if (t >= NN * NN) return;
    int a = t / NN, b = t - a * NN;
    const float* h0m = hm;
    const float* h1m = hm + NN * NN;
    const float* h2m = hm + 2 * NN * NN;
    float base = -h1m[t] + hv[0] * h0m[t] + hv[1] * h2m[t]
               + sv[0] * swm[t] + dv[0] * dwm[t];

    int i = a & (LL - 1), j = b & (LL - 1);
    float pxs = 0.5f * (ph_dir(i, j, X, ivic, sb, 1, 3) + ph_dir(j, i, X, ivic, sb, 1, 3));
    float pys = 0.5f * (ph_dir(i, j, Y, ivic, sb, 0, 2) + ph_dir(j, i, Y, ivic, sb, 0, 2));
    float P = pxs + pys;
    float M = pxs - pys;

    float ph;
    bool ar = (a >= LL), br = (b >= LL);
    if (!ar && !br)      ph =  g[0] * P;
    else if (ar && br)   ph = -g[0] * P;
    else                 ph = fS[0] * P + fD[0] * M;

    d_A[t] = base + ph;
}

__global__ void init_vt() {
    int t = blockIdx.x * blockDim.x + threadIdx.x;
    if (t >= NN * NN) return;
    int r = t / NN, c = t - r * NN;
    d_Vt[t] = (r == c) ? 1.f : 0.f;
}

__global__ void zero_acc() {
    d_accLog[0] = 0.0;
    d_barCnt = 0;
    d_barGen = 0;
}

// ------------------- prefill rotation scalars for round 0 (parity buffer 0) ------------
__global__ void rot0_k() {
    int i = blockIdx.x * 256 + threadIdx.x;
    if (i >= LL) return;
    int p, q;
    if (i == 0) { p = 0; q = NN - 1; }
    else { p = i; q = NROUND - i; }
    d_rotA[0][i] = d_A[(size_t)p * NN + p];
    d_rotB[0][i] = d_A[(size_t)q * NN + q];
    d_rotC[0][i] = d_A[(size_t)p * NN + q];
}

// ------------------- grid-wide software barrier (co-resident grid) -------------------
__device__ __forceinline__ void gsync(unsigned target) {
    __syncthreads();
    if (threadIdx.x == 0) {
        __threadfence();
        if (atomicAdd(&d_barCnt, 1u) == NBLK - 1) {
            d_barCnt = 0;
            __threadfence();
            d_barGen = target;
        } else {
            while (d_barGen < target) __nanosleep(32);
        }
    }
    __syncthreads();
}

// column map for round r: partner column jp, pair index pidx, p/q role
__device__ __forceinline__ void colmap(int j, int r, int& jp, int& pidx, bool& prole) {
    if (j == NN - 1) { jp = r; prole = false; pidx = 0; }
    else {
        int u = j - r; if (u < 0) u += NROUND;
        if (u == 0) { jp = NN - 1; prole = true; pidx = 0; }
        else {
            int t2 = 2 * r - j;
            if (t2 < 0)       t2 += NROUND;
            if (t2 >= NROUND) t2 -= NROUND;
            jp = t2;
            prole = (u <= 1023);
            pidx = prole ? u : NROUND - u;
        }
    }
}

// ------------------- persistent Jacobi: ONE grid barrier per round -------------------
// Block bi owns pairs bi and bi+NBLK. Rotation scalars for round r were deposited into
// compact parity-buffered arrays by round r-1's mix phase; every block redundantly
// computes all 1024 (c,s) from them (hot-L2 broadcast), so no coefficient publication
// barrier is needed. All cross-block reads see pre-round state; writes are disjoint.
__global__ __launch_bounds__(TPB, 4) void jacobi_k() {
    __shared__ float  r0p[NN], r0q[NN], r1p[NN], r1q[NN];
    __shared__ float2 scs[LL];
    unsigned bar = 0;

    for (int sw = 0; sw < NSWEEP; sw++)
    for (int r = 0; r < NROUND; r++) {
        int par = (sw + r) & 1;                // NROUND odd -> global round parity
        const float* rdA = d_rotA[par];
        const float* rdB = d_rotB[par];
        const float* rdC = d_rotC[par];
        float* wrA = d_rotA[par ^ 1];
        float* wrB = d_rotB[par ^ 1];
        float* wrC = d_rotC[par ^ 1];

        // ---- compute ALL pair rotations from compact scalars ----
        for (int k = threadIdx.x; k < LL; k += TPB) {
            float app = __ldcg(&rdA[k]);
            float aqq = __ldcg(&rdB[k]);
            float apq = __ldcg(&rdC[k]);
            float c = 1.f, s = 0.f;
            if (apq != 0.0f) {
                float tau = (aqq - app) / (2.f * apq);
                float t = (tau >= 0.f ? 1.f : -1.f) / (fabsf(tau) + sqrtf(1.f + tau * tau));
                c = rsqrtf(1.f + t * t);
                s = t * c;
            }
            scs[k] = make_float2(c, s);
        }
        __syncthreads();

        // ---- own pair rows & coefficients ----
        int i0 = blockIdx.x, i1 = blockIdx.x + NBLK;
        int p0, q0;
        if (i0 == 0) { p0 = r; q0 = NN - 1; }
        else { p0 = (i0 + r) % NROUND; q0 = (NROUND - i0 + r) % NROUND; }
        int p1 = (i1 + r) % NROUND;
        int q1 = (NROUND - i1 + r) % NROUND;
        float2 cs0 = scs[i0], cs1 = scs[i1];
        float c0 = cs0.x, s0 = cs0.y, c1 = cs1.x, s1 = cs1.y;

        // ---- stage: rotate both pairs' A rows into smem ----
        {
            const float4* A0p = (const float4*)(d_A + (size_t)p0 * NN);
            const float4* A0q = (const float4*)(d_A + (size_t)q0 * NN);
            const float4* A1p = (const float4*)(d_A + (size_t)p1 * NN);
            const float4* A1q = (const float4*)(d_A + (size_t)q1 * NN);
            float4* s0p = (float4*)r0p; float4* s0q = (float4*)r0q;
            float4* s1p = (float4*)r1p; float4* s1q = (float4*)r1q;
            #pragma unroll
            for (int it = 0; it < NN / 4 / TPB; it++) {
                int j4 = threadIdx.x + it * TPB;
                float4 a0 = __ldcg(&A0p[j4]);
                float4 b0 = __ldcg(&A0q[j4]);
                float4 a1 = __ldcg(&A1p[j4]);
                float4 b1 = __ldcg(&A1q[j4]);
                float4 t0p, t0q, t1p, t1q;
                t0p.x = c0*a0.x - s0*b0.x;  t0q.x = s0*a0.x + c0*b0.x;
                t0p.y = c0*a0.y - s0*b0.y;  t0q.y = s0*a0.y + c0*b0.y;
                t0p.z = c0*a0.z - s0*b0.z;  t0q.z = s0*a0.z + c0*b0.z;
                t0p.w = c0*a0.w - s0*b0.w;  t0q.w = s0*a0.w + c0*b0.w;
                t1p.x = c1*a1.x - s1*b1.x;  t1q.x = s1*a1.x + c1*b1.x;
                t1p.y = c1*a1.y - s1*b1.y;  t1q.y = s1*a1.y + c1*b1.y;
                t1p.z = c1*a1.z - s1*b1.z;  t1q.z = s1*a1.z + c1*b1.z;
                t1p.w = c1*a1.w - s1*b1.w;  t1q.w = s1*a1.w + c1*b1.w;
                s0p[j4] = t0p; s0q[j4] = t0q; s1p[j4] = t1p; s1q[j4] = t1q;
            }
        }

        // ---- Vt rows: rotate fully in place ----
        {
            float4* V0p = (float4*)(d_Vt + (size_t)p0 * NN);
            float4* V0q = (float4*)(d_Vt + (size_t)q0 * NN);
            float4* V1p = (float4*)(d_Vt + (size_t)p1 * NN);
            float4* V1q = (float4*)(d_Vt + (size_t)q1 * NN);
            #pragma unroll
            for (int it = 0; it < NN / 4 / TPB; it++) {
                int j4 = threadIdx.x + it * TPB;
                float4 a0 = __ldcg(&V0p[j4]);
                float4 b0 = __ldcg(&V0q[j4]);
                float4 n0p, n0q;
                n0p.x = c0*a0.x - s0*b0.x;  n0q.x = s0*a0.x + c0*b0.x;
                n0p.y = c0*a0.y - s0*b0.y;  n0q.y = s0*a0.y + c0*b0.y;
                n0p.z = c0*a0.z - s0*b0.z;  n0q.z = s0*a0.z + c0*b0.z;
                n0p.w = c0*a0.w - s0*b0.w;  n0q.w = s0*a0.w + c0*b0.w;
                __stcg(&V0p[j4], n0p);
                __stcg(&V0q[j4], n0q);
                float4 a1 = __ldcg(&V1p[j4]);
                float4 b1 = __ldcg(&V1q[j4]);
                float4 n1p, n1q;
                n1p.x = c1*a1.x - s1*b1.x;  n1q.x = s1*a1.x + c1*b1.x;
                n1p.y = c1*a1.y - s1*b1.y;  n1q.y = s1*a1.y + c1*b1.y;
                n1p.z = c1*a1.z - s1*b1.z;  n1q.z = s1*a1.z + c1*b1.z;
                n1p.w = c1*a1.w - s1*b1.w;  n1q.w = s1*a1.w + c1*b1.w;
                __stcg(&V1p[j4], n1p);
                __stcg(&V1q[j4], n1q);
            }
        }
        __syncthreads();

        // ---- mix phase: apply all column rotations, write 4 A rows ----
        {
            float* A0p = d_A + (size_t)p0 * NN;
            float* A0q = d_A + (size_t)q0 * NN;
            float* A1p = d_A + (size_t)p1 * NN;
            float* A1q = d_A + (size_t)q1 * NN;
            #pragma unroll
            for (int it = 0; it < NN / TPB; it++) {
                int j = threadIdx.x + it * TPB;
                int jp, pidx; bool prole;
                colmap(j, r, jp, pidx, prole);
                float2 cs = scs[pidx];
                float ccj = cs.x;
                float ssj = prole ? -cs.y : cs.y;
                __stcg(&A0p[j], ccj * r0p[j] + ssj * r0p[jp]);
                __stcg(&A0q[j], ccj * r0q[j] + ssj * r0q[jp]);
                __stcg(&A1p[j], ccj * r1p[j] + ssj * r1p[jp]);
                __stcg(&A1q[j], ccj * r1q[j] + ssj * r1q[jp]);
            }
        }

        // ---- handoff: deposit next round's rotation scalars (threads 0..3) ----
        if (threadIdx.x < 4) {
            int tid = threadIdx.x;
            int x;
            float* row;
            if (tid == 0)      { x = p0; row = r0p; }
            else if (tid == 1) { x = q0; row = r0q; }
            else if (tid == 2) { x = p1; row = r1p; }
            else               { x = q1; row = r1q; }
            int rn = (r + 1 == NROUND) ? 0 : (r + 1);
            int pidxN, partner; bool proleN;
            if (x == NN - 1) { pidxN = 0; proleN = false; partner = rn; }
            else {
                int u = x - rn; if (u < 0) u += NROUND;
                if (u == 0) { pidxN = 0; proleN = true; partner = NN - 1; }
                else {
                    int t2 = 2 * rn - x;
                    if (t2 < 0)       t2 += NROUND;
                    if (t2 >= NROUND) t2 -= NROUND;
                    partner = t2;
                    proleN = (u <= 1023);
                    pidxN = proleN ? u : NROUND - u;
                }
            }
            // final mixed value of row x at column j (same arithmetic as mix phase)
            int jp, pidx; bool prole;
            colmap(x, r, jp, pidx, prole);
            float2 cs = scs[pidx];
            float ssj = prole ? -cs.y : cs.y;
            float diag = cs.x * row[x] + ssj * row[jp];
            if (proleN) {
                __stcg(&wrA[pidxN], diag);
                colmap(partner, r, jp, pidx, prole);
                cs = scs[pidx];
                ssj = prole ? -cs.y : cs.y;
                __stcg(&wrC[pidxN], cs.x * row[partner] + ssj * row[jp]);
            } else {
                __stcg(&wrB[pidxN], diag);
            }
        }
        gsync(++bar);
    }
}

// ------------------- select 1024 smallest eigenvalues (rank selection) -------------------
__global__ void sel_k() {
    __shared__ float ev[NN];
    int t = threadIdx.x;  // 1024
    ev[t]      = d_A[(size_t)t * NN + t];
    ev[t + LL] = d_A[(size_t)(t + LL) * NN + (t + LL)];
    __syncthreads();
    for (int kk = 0; kk < 2; kk++) {
        int k = t + kk * LL;
        float v = ev[k];
        int rank = 0;
        for (int j = 0; j < NN; j++) {
            float u = ev[j];
            rank += (u < v) || (u == v && j < k);
        }
        if (rank < LL) d_sel[rank] = k;
    }
}

// ------------------- gather selected eigenvector rows -------------------
__global__ void gather2_k() {
    int t = blockIdx.x * 256 + threadIdx.x;
    if (t >= LL * NN) return;
    int c = t >> 11, k = t & (NN - 1);
    d_B2[t] = d_Vt[(size_t)d_sel[c] * NN + k];
}

__global__ void gatherB_k(const int* occ) {
    int t = blockIdx.x * 256 + threadIdx.x;
    if (t >= LL * LL) return;
    int c = t >> 10, rr = t & 1023;
    d_B[t] = d_B2[(size_t)c * NN + occ[rr]];
}

// ------------------- Gram = S * S^T (fp64 accumulate); which=0: B (K=1024)->G, 1: B2 (K=2048)->G2
__global__ void gram_k(int which) {
    __shared__ float As[16][17], Bs[16][17];
    const float* S = which ? d_B2 : d_B;
    double* G = which ? d_G2 : d_G;
    int K = which ? NN : LL;
    int tx = threadIdx.x, ty = threadIdx.y;
    int row = blockIdx.y * 16 + ty;
    int col = blockIdx.x * 16 + tx;
    double acc = 0.0;
    for (int kk = 0; kk < K; kk += 16) {
        As[ty][tx] = S[(size_t)(blockIdx.y * 16 + ty) * K + kk + tx];
        Bs[ty][tx] = S[(size_t)(blockIdx.x * 16 + ty) * K + kk + tx];
        __syncthreads();
#pragma unroll
        for (int k2 = 0; k2 < 16; k2++)
            acc += (double)As[ty][k2] * (double)Bs[tx][k2];
        __syncthreads();
    }
    G[(size_t)row * LL + col] = acc;
}

// ------------------- blocked fp64 Cholesky (nb=64); which selects matrix; sign on logdet ----
__global__ void potf2_k(int t, int which) {
    __shared__ double S[64][64];
    __shared__ double piv;
    double* G = which ? d_G2 : d_G;
    double sgn = which ? -1.0 : 1.0;
    int o = t * 64;
    int tid = threadIdx.x;  // 64 threads
    for (int r = 0; r < 64; r++) S[r][tid] = G[(size_t)(o + r) * LL + (o + tid)];
    __syncthreads();
    for (int k = 0; k < 64; k++) {
        if (tid == 0) {
            double dk = S[k][k];
            if (dk < 1e-250) dk = 1e-250;
            piv = sqrt(dk);
            S[k][k] = piv;
        }
        __syncthreads();
        double pv = piv;
        if (tid > k) S[tid][k] /= pv;
        __syncthreads();
        if (tid > k) {
            double lik = S[tid][k];
            for (int j = k + 1; j <= tid; j++) S[tid][j] -= lik * S[j][k];
        }
        __syncthreads();
    }
    if (tid == 0) {
        double ls = 0.0;
        for (int k = 0; k < 64; k++) ls += log(S[k][k]);
        d_accLog[0] += sgn * ls;   // sequential potf2 kernels: deterministic
    }
    for (int r = 0; r < 64; r++) G[(size_t)(o + r) * LL + (o + tid)] = S[r][tid];
}

__global__ void trsm_k(int t, int which) {
    __shared__ double L11[64][64];
    double* G = which ? d_G2 : d_G;
    int o = t * 64;
    int m0 = o + 64;
    int tid = threadIdx.x;  // 64
    {
        int r = tid;
        for (int c = 0; c < 64; c++) L11[r][c] = G[(size_t)(o + r) * LL + (o + c)];
    }
    __syncthreads();
    int row = m0 + blockIdx.x * 64 + tid;
    if (row < LL) {
        double xv[64];
        double* grow = &G[(size_t)row * LL + o];
        for (int c = 0; c < 64; c++) {
            double acc = grow[c];
            for (int k = 0; k < c; k++) acc -= xv[k] * L11[c][k];
            xv[c] = acc / L11[c][c];
        }
        for (int c = 0; c < 64; c++) grow[c] = xv[c];
    }
}

__global__ void syrk_k(int t, int which) {
    __shared__ double As[16][17], Bs[16][17];
    double* G = which ? d_G2 : d_G;
    int o = t * 64, m0 = o + 64;
    int tx = threadIdx.x, ty = threadIdx.y;
    int y = m0 + blockIdx.y * 16 + ty;
    int x = m0 + blockIdx.x * 16 + tx;
    double acc = 0.0;
    for (int kk = 0; kk < 64; kk += 16) {
        As[ty][tx] = G[(size_t)(m0 + blockIdx.y * 16 + ty) * LL + (o + kk + tx)];
        Bs[ty][tx] = G[(size_t)(m0 + blockIdx.x * 16 + ty) * LL + (o + kk + tx)];
        __syncthreads();
#pragma unroll
        for (int k2 = 0; k2 < 16; k2++) acc += As[ty][k2] * Bs[tx][k2];
        __syncthreads();
    }
    G[(size_t)y * LL + x] -= acc;
}

// ------------------- fused Jastrow + phonon quadratic forms -------------------
__global__ __launch_bounds__(256) void quad_k(const float* Sz, const float* X, const float* Y,
                                              const float* Js, const float* JcX, const float* JcY,
                                              const float* pXX, const float* pXY, const float* pYY,
                                              const float* sb) {
    __shared__ float sJs[289], sJcX[289], sJcY[289], sXX[289], sXY[289], sYY[289];
    __shared__ double red[256];
    int tid = threadIdx.x;
    for (int k = tid; k < 289; k += 256) {
        sJs[k]  = (k < 288) ? Js[k]  : 0.f;                    // pad_front=False
        sXX[k]  = (k < 288) ? pXX[k] : 0.f;
        sXY[k]  = (k < 288) ? pXY[k] : 0.f;
        sYY[k]  = (k < 288) ? pYY[k] : 0.f;
        sJcX[k] = (k == 0 || k >= 288) ? 0.f : JcX[k - 1];     // pad_front=True
        sJcY[k] = (k == 0 || k >= 288) ? 0.f : JcY[k - 1];
    }
    __syncthreads();
    int i = blockIdx.x;
    float xi = X[i], yi = Y[i], szi = Sz[i];
    int ix = i >> 5, iy = i & 31;
    double lsum = 0.0;
    for (int j = tid; j < LL; j += 256) {
        int jx = j >> 5, jy = j & 31;
        int dx = (jx - ix) & 31; if (dx > 16) dx = 32 - dx;
        int dy = (jy - iy) & 31; if (dy > 16) dy = 32 - dy;
        int idx = dx * 17 + dy;
        float sbij = sb[i * LL + j];
        float xj = X[j], yj = Y[j], szj = Sz[j];
        float v = szi * szj * (sJs[idx] + (sJcX[idx] * (xi - xj) + sJcY[idx] * (yi - yj)) * sbij)
                + xi * sXX[idx] * xj
                + (yi * xj + xi * yj) * sXY[idx]
                + yi * sYY[idx] * yj;
        lsum += (double)v;
    }
    red[tid] = lsum;
    __syncthreads();
    for (int st = 128; st > 0; st >>= 1) {
        if (tid < st) red[tid] += red[tid + st];
        __syncthreads();
    }
    if (tid == 0) d_part[i] = red[0];
}

__global__ void gauss_k(const float* X, const float* Y, const float* sx, const float* sy,
                        const float* zx, const float* zy, const float* xr, const float* yr) {
    __shared__ double red[1024];
    int t = threadIdx.x;
    float gx = X[t] - zx[0] * sx[t];
    float gy = Y[t] - zy[0] * sy[t];
    red[t] = -0.5 * (double)xr[0] * (double)gx * (double)gx
             - 0.5 * (double)yr[0] * (double)gy * (double)gy;
    __syncthreads();
    for (int st = 512; st > 0; st >>= 1) {
        if (t < st) red[t] += red[t + st];
        __syncthreads();
    }
    if (t == 0) d_accGauss[0] = red[0];
}

__global__ void final_k(float* out) {
    __shared__ double red[1024];
    int t = threadIdx.x;
    red[t] = d_part[t];
    __syncthreads();
    for (int st = 512; st > 0; st >>= 1) {
        if (t < st) red[t] += red[t + st];
        __syncthreads();
    }
    if (t == 0) out[0] = (float)(red[0] + d_accGauss[0] + d_accLog[0]);
}

// ------------------- launch -------------------
extern "C" void kernel_launch(void* const* d_in, const int* in_sizes, int n_in,
                              void* d_out, int out_size) {
    const int*   occ  = (const int*)d_in[0];
    // d_in[1] = xloc (unused by reference)
    const float* Sz   = (const float*)d_in[2];
    const float* X    = (const float*)d_in[3];
    const float* Y    = (const float*)d_in[4];
    const float* hv   = (const float*)d_in[5];
    const float* sv   = (const float*)d_in[6];
    const float* dv   = (const float*)d_in[7];
    const float* Js   = (const float*)d_in[8];
    const float* JcX  = (const float*)d_in[9];
    const float* JcY  = (const float*)d_in[10];
    const float* pXX  = (const float*)d_in[11];
    const float* pXY  = (const float*)d_in[12];
    const float* pYY  = (const float*)d_in[13];
    const float* g    = (const float*)d_in[14];
    const float* fS   = (const float*)d_in[15];
    const float* fD   = (const float*)d_in[16];
    const float* zx   = (const float*)d_in[17];
    const float* zy   = (const float*)d_in[18];
    const float* xr   = (const float*)d_in[19];
    const float* yr   = (const float*)d_in[20];
    const float* hm   = (const float*)d_in[21];
    const float* swm  = (const float*)d_in[22];
    const float* dwm  = (const float*)d_in[23];
    const int*   ivic = (const int*)d_in[24];
    const float* sb   = (const float*)d_in[25];
    const float* sx   = (const float*)d_in[26];
    const float* sy   = (const float*)d_in[27];
    float* out = (float*)d_out;

    int nb = (NN * NN + 255) / 256;
    build_H<<<nb, 256>>>(hm, swm, dwm, hv, sv, dv, g, fS, fD, X, Y, ivic, sb);
    init_vt<<<nb, 256>>>();
    zero_acc<<<1, 1>>>();
    rot0_k<<<4, 256>>>();

    // single persistent launch: all NSWEEP x NROUND Jacobi rounds, 1 barrier/round
    jacobi_k<<<NBLK, TPB>>>();

    sel_k<<<1, 1024>>>();
    gather2_k<<<(LL * NN + 255) / 256, 256>>>();
    gatherB_k<<<(LL * LL + 255) / 256, 256>>>(occ);
    gram_k<<<dim3(64, 64), dim3(16, 16)>>>(0);
    gram_k<<<dim3(64, 64), dim3(16, 16)>>>(1);

    for (int which = 0; which < 2; which++) {
        for (int t = 0; t < 16; t++) {
            potf2_k<<<1, 64>>>(t, which);
            int m = LL - (t + 1) * 64;
            if (m > 0) {
                trsm_k<<<m / 64, 64>>>(t, which);
                syrk_k<<<dim3(m / 16, m / 16), dim3(16, 16)>>>(t, which);
            }
        }
    }

    quad_k<<<LL, 256>>>(Sz, X, Y, Js, JcX, JcY, pXX, pXY, pYY, sb);
    gauss_k<<<1, 1024>>>(X, Y, sx, sy, zx, zy, xr, yr);
    final_k<<<1, 1024>>>(out);
}

// round 15
// speedup vs baseline: 1.3794x; 1.0092x over previous
#include <cuda_runtime.h>
#include <math.h>

#define NN 2048
#define LL 1024
#define NROUND 2047
#define NSWEEP 8
#define NBLK 1024
#define TPB 128

// ------------------- static device scratch (no runtime allocation) -------------------
__device__ float  d_A[NN * NN];      // working symmetric matrix -> diagonalized
__device__ float  d_Vt[NN * NN];     // accumulated V^T (row k = eigenvector k)
__device__ float  d_rotA[2][LL];     // next-round rotation scalars: app (parity buffered)
__device__ float  d_rotB[2][LL];     // aqq
__device__ float  d_rotC[2][LL];     // apq
__device__ int    d_sel[LL];         // indices of 1024 smallest eigenvalues
__device__ float  d_B2[LL * NN];     // selected eigenvector rows: B2[c][k] = Vt[sel[c]][k]
__device__ float  d_B[LL * LL];      // B[c][r] = B2[c][occ[r]]
__device__ double d_G[LL * LL];      // Gram of B   (fp64) -> Cholesky
__device__ double d_G2[LL * LL];     // Gram of B2  (fp64) -> Cholesky (orthog. correction)
__device__ double d_accLog[1];       // +sum log L_ii (G)  - sum log L_ii (G2)
__device__ double d_accGauss[1];
__device__ double d_part[LL];
__device__ unsigned d_barCnt;
__device__ volatile unsigned d_barGen;

// ------------------- build H (symmetrized, as jnp.linalg.eigh does) -------------------
__device__ __forceinline__ float ph_dir(int i, int j, const float* Ph, const int* ivic,
                                        const float* sb, int da, int db) {
    int n1 = ivic[i * 4 + da];
    int n2 = ivic[i * 4 + db];
    if (j == n1 || j == n2) return (Ph[j] - Ph[i]) * sb[i * LL + j];
    return 0.f;
}

__global__ void build_H(const float* hm, const float* swm, const float* dwm,
                        const float* hv, const float* sv, const float* dv,
                        const float* g, const float* fS, const float* fD,
                        const float* X, const float* Y,
                        const int* ivic, const float* sb) {
    int t = blockIdx.x * blockDim.x + threadIdx.x;
    if (t >= NN * NN) return;
    int a = t / NN, b = t - a * NN;
    const float* h0m = hm;
    const float* h1m = hm + NN * NN;
    const float* h2m = hm + 2 * NN * NN;
    float base = -h1m[t] + hv[0] * h0m[t] + hv[1] * h2m[t]
               + sv[0] * swm[t] + dv[0] * dwm[t];

    int i = a & (LL - 1), j = b & (LL - 1);
    float pxs = 0.5f * (ph_dir(i, j, X, ivic, sb, 1, 3) + ph_dir(j, i, X, ivic, sb, 1, 3));
    float pys = 0.5f * (ph_dir(i, j, Y, ivic, sb, 0, 2) + ph_dir(j, i, Y, ivic, sb, 0, 2));
    float P = pxs + pys;
    float M = pxs - pys;

    float ph;
    bool ar = (a >= LL), br = (b >= LL);
    if (!ar && !br)      ph =  g[0] * P;
    else if (ar && br)   ph = -g[0] * P;
    else                 ph = fS[0] * P + fD[0] * M;

    d_A[t] = base + ph;
}

__global__ void init_vt() {
    int t = blockIdx.x * blockDim.x + threadIdx.x;
    if (t >= NN * NN) return;
    int r = t / NN, c = t - r * NN;
    d_Vt[t] = (r == c) ? 1.f : 0.f;
}

__global__ void zero_acc() {
    d_accLog[0] = 0.0;
    d_barCnt = 0;
    d_barGen = 0;
}

// ------------------- prefill rotation scalars for round 0 (parity buffer 0) ------------
__global__ void rot0_k() {
    int i = blockIdx.x * 256 + threadIdx.x;
    if (i >= LL) return;
    int p, q;
    if (i == 0) { p = 0; q = NN - 1; }
    else { p = i; q = NROUND - i; }
    d_rotA[0][i] = d_A[(size_t)p * NN + p];
    d_rotB[0][i] = d_A[(size_t)q * NN + q];
    d_rotC[0][i] = d_A[(size_t)p * NN + q];
}

// ------------------- grid-wide software barrier (co-resident grid) -------------------
__device__ __forceinline__ void gsync(unsigned target) {
    __syncthreads();
    if (threadIdx.x == 0) {
        __threadfence();
        if (atomicAdd(&d_barCnt, 1u) == NBLK - 1) {
            d_barCnt = 0;
            __threadfence();
            d_barGen = target;
        } else {
            while (d_barGen < target) __nanosleep(32);
        }
    }
    __syncthreads();
}

// column map for round r: partner column jp, pair index pidx, p/q role
__device__ __forceinline__ void colmap(int j, int r, int& jp, int& pidx, bool& prole) {
    if (j == NN - 1) { jp = r; prole = false; pidx = 0; }
    else {
        int u = j - r; if (u < 0) u += NROUND;
        if (u == 0) { jp = NN - 1; prole = true; pidx = 0; }
        else {
            int t2 = 2 * r - j;
            if (t2 < 0)       t2 += NROUND;
            if (t2 >= NROUND) t2 -= NROUND;
            jp = t2;
            prole = (u <= 1023);
            pidx = prole ? u : NROUND - u;
        }
    }
}

// ------------------- persistent Jacobi: ONE pair per block, 1 barrier/round ------------
// Block bi owns pair bi. Rotation scalars for round r were deposited into compact
// parity-buffered arrays by round r-1's mix phase; every block redundantly computes
// all 1024 (c,s) from them (hot-L2 broadcast). Writes are ownership-disjoint.
__global__ __launch_bounds__(TPB, 8) void jacobi_k() {
    __shared__ float  r0p[NN], r0q[NN];
    __shared__ float2 scs[LL];
    unsigned bar = 0;

    for (int sw = 0; sw < NSWEEP; sw++)
    for (int r = 0; r < NROUND; r++) {
        int par = (sw + r) & 1;                // NROUND odd -> global round parity
        const float* rdA = d_rotA[par];
        const float* rdB = d_rotB[par];
        const float* rdC = d_rotC[par];
        float* wrA = d_rotA[par ^ 1];
        float* wrB = d_rotB[par ^ 1];
        float* wrC = d_rotC[par ^ 1];

        // ---- compute ALL pair rotations from compact scalars ----
        #pragma unroll
        for (int kk = 0; kk < LL / TPB; kk++) {
            int k = threadIdx.x + kk * TPB;
            float app = __ldcg(&rdA[k]);
            float aqq = __ldcg(&rdB[k]);
            float apq = __ldcg(&rdC[k]);
            float c = 1.f, s = 0.f;
            if (apq != 0.0f) {
                float tau = (aqq - app) / (2.f * apq);
                float t = (tau >= 0.f ? 1.f : -1.f) / (fabsf(tau) + sqrtf(1.f + tau * tau));
                c = rsqrtf(1.f + t * t);
                s = t * c;
            }
            scs[k] = make_float2(c, s);
        }
        __syncthreads();

        // ---- own pair rows & coefficients ----
        int i0 = blockIdx.x;
        int p0, q0;
        if (i0 == 0) { p0 = r; q0 = NN - 1; }
        else { p0 = (i0 + r) % NROUND; q0 = (NROUND - i0 + r) % NROUND; }
        float2 cs0 = scs[i0];
        float c0 = cs0.x, s0 = cs0.y;

        // ---- stage: rotate my pair's A rows into smem ----
        {
            const float4* A0p = (const float4*)(d_A + (size_t)p0 * NN);
            const float4* A0q = (const float4*)(d_A + (size_t)q0 * NN);
            float4* s0p = (float4*)r0p; float4* s0q = (float4*)r0q;
            #pragma unroll
            for (int it = 0; it < NN / 4 / TPB; it++) {
                int j4 = threadIdx.x + it * TPB;
                float4 a0 = __ldcg(&A0p[j4]);
                float4 b0 = __ldcg(&A0q[j4]);
                float4 t0p, t0q;
                t0p.x = c0*a0.x - s0*b0.x;  t0q.x = s0*a0.x + c0*b0.x;
                t0p.y = c0*a0.y - s0*b0.y;  t0q.y = s0*a0.y + c0*b0.y;
                t0p.z = c0*a0.z - s0*b0.z;  t0q.z = s0*a0.z + c0*b0.z;
                t0p.w = c0*a0.w - s0*b0.w;  t0q.w = s0*a0.w + c0*b0.w;
                s0p[j4] = t0p; s0q[j4] = t0q;
            }
        }

        // ---- Vt rows: rotate fully in place ----
        {
            float4* V0p = (float4*)(d_Vt + (size_t)p0 * NN);
            float4* V0q = (float4*)(d_Vt + (size_t)q0 * NN);
            #pragma unroll
            for (int it = 0; it < NN / 4 / TPB; it++) {
                int j4 = threadIdx.x + it * TPB;
                float4 a0 = __ldcg(&V0p[j4]);
                float4 b0 = __ldcg(&V0q[j4]);
                float4 n0p, n0q;
                n0p.x = c0*a0.x - s0*b0.x;  n0q.x = s0*a0.x + c0*b0.x;
                n0p.y = c0*a0.y - s0*b0.y;  n0q.y = s0*a0.y + c0*b0.y;
                n0p.z = c0*a0.z - s0*b0.z;  n0q.z = s0*a0.z + c0*b0.z;
                n0p.w = c0*a0.w - s0*b0.w;  n0q.w = s0*a0.w + c0*b0.w;
                __stcg(&V0p[j4], n0p);
                __stcg(&V0q[j4], n0q);
            }
        }
        __syncthreads();

        // ---- mix phase: apply all column rotations, write 2 A rows ----
        {
            float* A0p = d_A + (size_t)p0 * NN;
            float* A0q = d_A + (size_t)q0 * NN;
            #pragma unroll
            for (int it = 0; it < NN / TPB; it++) {
                int j = threadIdx.x + it * TPB;
                int jp, pidx; bool prole;
                colmap(j, r, jp, pidx, prole);
                float2 cs = scs[pidx];
                float ccj = cs.x;
                float ssj = prole ? -cs.y : cs.y;
                __stcg(&A0p[j], ccj * r0p[j] + ssj * r0p[jp]);
                __stcg(&A0q[j], ccj * r0q[j] + ssj * r0q[jp]);
            }
        }

        // ---- handoff: deposit next round's rotation scalars (threads 0..1) ----
        if (threadIdx.x < 2) {
            int tid = threadIdx.x;
            int x;
            float* row;
            if (tid == 0) { x = p0; row = r0p; }
            else          { x = q0; row = r0q; }
            int rn = (r + 1 == NROUND) ? 0 : (r + 1);
            int pidxN, partner; bool proleN;
            if (x == NN - 1) { pidxN = 0; proleN = false; partner = rn; }
            else {
                int u = x - rn; if (u < 0) u += NROUND;
                if (u == 0) { pidxN = 0; proleN = true; partner = NN - 1; }
                else {
                    int t2 = 2 * rn - x;
                    if (t2 < 0)       t2 += NROUND;
                    if (t2 >= NROUND) t2 -= NROUND;
                    partner = t2;
                    proleN = (u <= 1023);
                    pidxN = proleN ? u : NROUND - u;
                }
            }
            // final mixed value of row x at column j (same arithmetic as mix phase)
            int jp, pidx; bool prole;
            colmap(x, r, jp, pidx, prole);
            float2 cs = scs[pidx];
            float ssj = prole ? -cs.y : cs.y;
            float diag = cs.x * row[x] + ssj * row[jp];
            if (proleN) {
                __stcg(&wrA[pidxN], diag);
                colmap(partner, r, jp, pidx, prole);
                cs = scs[pidx];
                ssj = prole ? -cs.y : cs.y;
                __stcg(&wrC[pidxN], cs.x * row[partner] + ssj * row[jp]);
            } else {
                __stcg(&wrB[pidxN], diag);
            }
        }
        gsync(++bar);
    }
}

// ------------------- select 1024 smallest eigenvalues (rank selection) -------------------
__global__ void sel_k() {
    __shared__ float ev[NN];
    int t = threadIdx.x;  // 1024
    ev[t]      = d_A[(size_t)t * NN + t];
    ev[t + LL] = d_A[(size_t)(t + LL) * NN + (t + LL)];
    __syncthreads();
    for (int kk = 0; kk < 2; kk++) {
        int k = t + kk * LL;
        float v = ev[k];
        int rank = 0;
        for (int j = 0; j < NN; j++) {
            float u = ev[j];
            rank += (u < v) || (u == v && j < k);
        }
        if (rank < LL) d_sel[rank] = k;
    }
}

// ------------------- gather selected eigenvector rows -------------------
__global__ void gather2_k() {
    int t = blockIdx.x * 256 + threadIdx.x;
    if (t >= LL * NN) return;
    int c = t >> 11, k = t & (NN - 1);
    d_B2[t] = d_Vt[(size_t)d_sel[c] * NN + k];
}

__global__ void gatherB_k(const int* occ) {
    int t = blockIdx.x * 256 + threadIdx.x;
    if (t >= LL * LL) return;
    int c = t >> 10, rr = t & 1023;
    d_B[t] = d_B2[(size_t)c * NN + occ[rr]];
}

// ------------------- Gram = S * S^T (fp64 accumulate); which=0: B (K=1024)->G, 1: B2 (K=2048)->G2
__global__ void gram_k(int which) {
    __shared__ float As[16][17], Bs[16][17];
    const float* S = which ? d_B2 : d_B;
    double* G = which ? d_G2 : d_G;
    int K = which ? NN : LL;
    int tx = threadIdx.x, ty = threadIdx.y;
    int row = blockIdx.y * 16 + ty;
    int col = blockIdx.x * 16 + tx;
    double acc = 0.0;
    for (int kk = 0; kk < K; kk += 16) {
        As[ty][tx] = S[(size_t)(blockIdx.y * 16 + ty) * K + kk + tx];
        Bs[ty][tx] = S[(size_t)(blockIdx.x * 16 + ty) * K + kk + tx];
        __syncthreads();
#pragma unroll
        for (int k2 = 0; k2 < 16; k2++)
            acc += (double)As[ty][k2] * (double)Bs[tx][k2];
        __syncthreads();
    }
    G[(size_t)row * LL + col] = acc;
}

// ------------------- blocked fp64 Cholesky (nb=64); which selects matrix; sign on logdet ----
__global__ void potf2_k(int t, int which) {
    __shared__ double S[64][64];
    __shared__ double piv;
    double* G = which ? d_G2 : d_G;
    double sgn = which ? -1.0 : 1.0;
    int o = t * 64;
    int tid = threadIdx.x;  // 64 threads
    for (int r = 0; r < 64; r++) S[r][tid] = G[(size_t)(o + r) * LL + (o + tid)];
    __syncthreads();
    for (int k = 0; k < 64; k++) {
        if (tid == 0) {
            double dk = S[k][k];
            if (dk < 1e-250) dk = 1e-250;
            piv = sqrt(dk);
            S[k][k] = piv;
        }
        __syncthreads();
        double pv = piv;
        if (tid > k) S[tid][k] /= pv;
        __syncthreads();
        if (tid > k) {
            double lik = S[tid][k];
            for (int j = k + 1; j <= tid; j++) S[tid][j] -= lik * S[j][k];
        }
        __syncthreads();
    }
    if (tid == 0) {
        double ls = 0.0;
        for (int k = 0; k < 64; k++) ls += log(S[k][k]);
        d_accLog[0] += sgn * ls;   // sequential potf2 kernels: deterministic
    }
    for (int r = 0; r < 64; r++) G[(size_t)(o + r) * LL + (o + tid)] = S[r][tid];
}

__global__ void trsm_k(int t, int which) {
    __shared__ double L11[64][64];
    double* G = which ? d_G2 : d_G;
    int o = t * 64;
    int m0 = o + 64;
    int tid = threadIdx.x;  // 64
    {
        int r = tid;
        for (int c = 0; c < 64; c++) L11[r][c] = G[(size_t)(o + r) * LL + (o + c)];
    }
    __syncthreads();
    int row = m0 + blockIdx.x * 64 + tid;
    if (row < LL) {
        double xv[64];
        double* grow = &G[(size_t)row * LL + o];
        for (int c = 0; c < 64; c++) {
            double acc = grow[c];
            for (int k = 0; k < c; k++) acc -= xv[k] * L11[c][k];
            xv[c] = acc / L11[c][c];
        }
        for (int c = 0; c < 64; c++) grow[c] = xv[c];
    }
}

__global__ void syrk_k(int t, int which) {
    __shared__ double As[16][17], Bs[16][17];
    double* G = which ? d_G2 : d_G;
    int o = t * 64, m0 = o + 64;
    int tx = threadIdx.x, ty = threadIdx.y;
    int y = m0 + blockIdx.y * 16 + ty;
    int x = m0 + blockIdx.x * 16 + tx;
    double acc = 0.0;
    for (int kk = 0; kk < 64; kk += 16) {
        As[ty][tx] = G[(size_t)(m0 + blockIdx.y * 16 + ty) * LL + (o + kk + tx)];
        Bs[ty][tx] = G[(size_t)(m0 + blockIdx.x * 16 + ty) * LL + (o + kk + tx)];
        __syncthreads();
#pragma unroll
        for (int k2 = 0; k2 < 16; k2++) acc += As[ty][k2] * Bs[tx][k2];
        __syncthreads();
    }
    G[(size_t)y * LL + x] -= acc;
}

// ------------------- fused Jastrow + phonon quadratic forms -------------------
__global__ __launch_bounds__(256) void quad_k(const float* Sz, const float* X, const float* Y,
                                              const float* Js, const float* JcX, const float* JcY,
                                              const float* pXX, const float* pXY, const float* pYY,
                                              const float* sb) {
    __shared__ float sJs[289], sJcX[289], sJcY[289], sXX[289], sXY[289], sYY[289];
    __shared__ double red[256];
    int tid = threadIdx.x;
    for (int k = tid; k < 289; k += 256) {
        sJs[k]  = (k < 288) ? Js[k]  : 0.f;                    // pad_front=False
        sXX[k]  = (k < 288) ? pXX[k] : 0.f;
        sXY[k]  = (k < 288) ? pXY[k] : 0.f;
        sYY[k]  = (k < 288) ? pYY[k] : 0.f;
        sJcX[k] = (k == 0 || k >= 288) ? 0.f : JcX[k - 1];     // pad_front=True
        sJcY[k] = (k == 0 || k >= 288) ? 0.f : JcY[k - 1];
    }
    __syncthreads();
    int i = blockIdx.x;
    float xi = X[i], yi = Y[i], szi = Sz[i];
    int ix = i >> 5, iy = i & 31;
    double lsum = 0.0;
    for (int j = tid; j < LL; j += 256) {
        int jx = j >> 5, jy = j & 31;
        int dx = (jx - ix) & 31; if (dx > 16) dx = 32 - dx;
        int dy = (jy - iy) & 31; if (dy > 16) dy = 32 - dy;
        int idx = dx * 17 + dy;
        float sbij = sb[i * LL + j];
        float xj = X[j], yj = Y[j], szj = Sz[j];
        float v = szi * szj * (sJs[idx] + (sJcX[idx] * (xi - xj) + sJcY[idx] * (yi - yj)) * sbij)
                + xi * sXX[idx] * xj
                + (yi * xj + xi * yj) * sXY[idx]
                + yi * sYY[idx] * yj;
        lsum += (double)v;
    }
    red[tid] = lsum;
    __syncthreads();
    for (int st = 128; st > 0; st >>= 1) {
        if (tid < st) red[tid] += red[tid + st];
        __syncthreads();
    }
    if (tid == 0) d_part[i] = red[0];
}

__global__ void gauss_k(const float* X, const float* Y, const float* sx, const float* sy,
                        const float* zx, const float* zy, const float* xr, const float* yr) {
    __shared__ double red[1024];
    int t = threadIdx.x;
    float gx = X[t] - zx[0] * sx[t];
    float gy = Y[t] - zy[0] * sy[t];
    red[t] = -0.5 * (double)xr[0] * (double)gx * (double)gx
             - 0.5 * (double)yr[0] * (double)gy * (double)gy;
    __syncthreads();
    for (int st = 512; st > 0; st >>= 1) {
        if (t < st) red[t] += red[t + st];
        __syncthreads();
    }
    if (t == 0) d_accGauss[0] = red[0];
}

__global__ void final_k(float* out) {
    __shared__ double red[1024];
    int t = threadIdx.x;
    red[t] = d_part[t];
    __syncthreads();
    for (int st = 512; st > 0; st >>= 1) {
        if (t < st) red[t] += red[t + st];
        __syncthreads();
    }
    if (t == 0) out[0] = (float)(red[0] + d_accGauss[0] + d_accLog[0]);
}

// ------------------- launch -------------------
extern "C" void kernel_launch(void* const* d_in, const int* in_sizes, int n_in,
                              void* d_out, int out_size) {
    const int*   occ  = (const int*)d_in[0];
    // d_in[1] = xloc (unused by reference)
    const float* Sz   = (const float*)d_in[2];
    const float* X    = (const float*)d_in[3];
    const float* Y    = (const float*)d_in[4];
    const float* hv   = (const float*)d_in[5];
    const float* sv   = (const float*)d_in[6];
    const float* dv   = (const float*)d_in[7];
    const float* Js   = (const float*)d_in[8];
    const float* JcX  = (const float*)d_in[9];
    const float* JcY  = (const float*)d_in[10];
    const float* pXX  = (const float*)d_in[11];
    const float* pXY  = (const float*)d_in[12];
    const float* pYY  = (const float*)d_in[13];
    const float* g    = (const float*)d_in[14];
    const float* fS   = (const float*)d_in[15];
    const float* fD   = (const float*)d_in[16];
    const float* zx   = (const float*)d_in[17];
    const float* zy   = (const float*)d_in[18];
    const float* xr   = (const float*)d_in[19];
    const float* yr   = (const float*)d_in[20];
    const float* hm   = (const float*)d_in[21];
    const float* swm  = (const float*)d_in[22];
    const float* dwm  = (const float*)d_in[23];
    const int*   ivic = (const int*)d_in[24];
    const float* sb   = (const float*)d_in[25];
    const float* sx   = (const float*)d_in[26];
    const float* sy   = (const float*)d_in[27];
    float* out = (float*)d_out;

    int nb = (NN * NN + 255) / 256;
    build_H<<<nb, 256>>>(hm, swm, dwm, hv, sv, dv, g, fS, fD, X, Y, ivic, sb);
    init_vt<<<nb, 256>>>();
    zero_acc<<<1, 1>>>();
    rot0_k<<<4, 256>>>();

    // single persistent launch: all NSWEEP x NROUND Jacobi rounds, 1 barrier/round
    jacobi_k<<<NBLK, TPB>>>();

    sel_k<<<1, 1024>>>();
    gather2_k<<<(LL * NN + 255) / 256, 256>>>();
    gatherB_k<<<(LL * LL + 255) / 256, 256>>>(occ);
    gram_k<<<dim3(64, 64), dim3(16, 16)>>>(0);
    gram_k<<<dim3(64, 64), dim3(16, 16)>>>(1);

    for (int which = 0; which < 2; which++) {
        for (int t = 0; t < 16; t++) {
            potf2_k<<<1, 64>>>(t, which);
            int m = LL - (t + 1) * 64;
            if (m > 0) {
                trsm_k<<<m / 64, 64>>>(t, which);
                syrk_k<<<dim3(m / 16, m / 16), dim3(16, 16)>>>(t, which);
            }
        }
    }

    quad_k<<<LL, 256>>>(Sz, X, Y, Js, JcX, JcY, pXX, pXY, pYY, sb);
    gauss_k<<<1, 1024>>>(X, Y, sx, sy, zx, zy, xr, yr);
    final_k<<<1, 1024>>>(out);
}